// round 15
// baseline (speedup 1.0000x reference)
#include <cuda_runtime.h>
#include <cstdint>

#define NAG   4096
#define TOPK  12
#define NSEL  13                 // extract 13, fix up ordering with real sqrt
#define NITEMS (NAG * TOPK)      // 49152
#define T1    256
#define EPT   16                 // elements per thread = 4096/256
#define CCAP  256                // per-row candidate capacity (smem)
#define IST   12                 // item stride (floats) in H1s/H2s/red

#define U64MAX 0xFFFFFFFFFFFFFFFFULL
typedef unsigned long long u64;

__device__ float g_W2t[64 * 128];        // [k][m]
__device__ float g_W3t[128 * 64];        // [k][o]

static __device__ __forceinline__ u64 u64min(u64 a, u64 b) { return (b < a) ? b : a; }

// ---- packed f32x2 helpers (bitwise identical to two scalar fmaf's) --------
static __device__ __forceinline__ u64 pk2(float lo, float hi) {
    u64 r;
    asm("mov.b64 %0, {%1, %2};" : "=l"(r) : "f"(lo), "f"(hi));
    return r;
}
static __device__ __forceinline__ u64 fma2(u64 a, u64 b, u64 c) {
    u64 d;
    asm("fma.rn.f32x2 %0, %1, %2, %3;" : "=l"(d) : "l"(a), "l"(b), "l"(c));
    return d;
}
static __device__ __forceinline__ float2 up2(u64 v) {
    float2 f;
    asm("mov.b64 {%0, %1}, %2;" : "=f"(f.x), "=f"(f.y) : "l"(v));
    return f;
}

// ---------------------------------------------------------------------------
// Kernel T: transpose W2 -> g_W2t [k][m], W3 -> g_W3t [k][o].
// Must run (and complete) before the fused kernel reads the weights.
// ---------------------------------------------------------------------------
__global__ void __launch_bounds__(T1) transpose_kernel(
    const float* __restrict__ W2, const float* __restrict__ W3)
{
    const int g = blockIdx.x * T1 + threadIdx.x;
    const int stride = gridDim.x * T1;
    for (int s = g; s < 128 * 64; s += stride) {
        const int m = s >> 6, k = s & 63;
        g_W2t[k * 128 + m] = W2[s];
    }
    for (int s = g; s < 64 * 128; s += stride) {
        const int o = s >> 7, m = s & 127;
        g_W3t[m * 64 + o] = W3[s];
    }
}

// ---------------------------------------------------------------------------
// Fully fused kernel: one block per agent row.
//  Phase 1 (proven): stream row (evict-first), threshold filter (max of 16
//    half-warp minima => >=16 candidates), smem candidate buffer, warp-0
//    13-pass exact extract-min + monotone-sqrt re-key fixup -> sidx[12].
//  Phase 2: 12-item MLP entirely in-block:
//    layer1: thread=(o, item-triple) -> H1s[64][12]
//    layer2: thread=(m, item-half), K=64, 3 f32x2 pairs  -> H2s[128][12]
//    layer3: thread=(o, k-half, pair-group), K=128 split; smem combine
//    layer4: per-o scalar partials -> red[64][12] -> 12-thread sum.
//  DRAM streaming of some blocks overlaps FFMA bursts of others.
// ---------------------------------------------------------------------------
__global__ void __launch_bounds__(T1) fused_all_kernel(
    const float* __restrict__ x,  const float* __restrict__ rp,
    const float* __restrict__ W1, const float* __restrict__ b1,
    const float* __restrict__ b2, const float* __restrict__ b3,
    const float* __restrict__ W4, const float* __restrict__ b4,
    float* __restrict__ out)
{
    __shared__ u64      scand[CCAP];          // 2 KB
    __shared__ float    H2s[128 * IST];       // 6 KB
    __shared__ float    H1s[64 * IST];        // 3 KB (reused as 'red')
    __shared__ float    part[2 * 64 * 6];     // 3 KB (layer3 k-split combine)
    __shared__ float    feats[12 * 8];
    __shared__ float    W1s[64 * 6];
    __shared__ float    b1s[64];
    __shared__ float    masks[12];
    __shared__ int      sidx[12];
    __shared__ unsigned tmin16[16];
    __shared__ unsigned sthresh;
    __shared__ int      scnt;

    const int tid  = threadIdx.x;
    const int w    = tid >> 5;
    const int lane = tid & 31;
    const int i    = blockIdx.x;
    const float* row = x + (size_t)i * (NAG * 4);

    for (int s = tid; s < 384; s += T1) W1s[s] = W1[s];
    if (tid < 64) b1s[tid] = b1[tid];
    if (tid == 0) scnt = 0;

    // ---------------- phase 1a: streaming filter (proven) ------------------
    unsigned sb[EPT];
#pragma unroll
    for (int t = 0; t < EPT; ++t) {
        const int j = tid + t * T1;
        const float2 v = __ldcs(reinterpret_cast<const float2*>(row + (size_t)j * 4));
        const float s = __fadd_rn(__fadd_rn(__fmul_rn(v.x, v.x), 1e-6f),
                                  __fadd_rn(__fmul_rn(v.y, v.y), 1e-6f));
        sb[t] = __float_as_uint(s);
    }

    unsigned mymin = sb[0];
#pragma unroll
    for (int t = 1; t < EPT; ++t) mymin = (sb[t] < mymin) ? sb[t] : mymin;

    unsigned h = mymin;
#pragma unroll
    for (int off = 1; off <= 8; off <<= 1) {
        const unsigned o = __shfl_xor_sync(0xffffffffu, h, off);
        h = (o < h) ? o : h;
    }
    if ((lane & 15) == 0) tmin16[w * 2 + (lane >> 4)] = h;
    __syncthreads();

    if (w == 0 && lane < 16) {
        const unsigned mx = __reduce_max_sync(0xFFFFu, tmin16[lane]);
        if (lane == 0) sthresh = mx;
    }
    __syncthreads();

    const unsigned thr = sthresh;
#pragma unroll
    for (int t = 0; t < EPT; ++t) {
        if (sb[t] <= thr) {
            const int pos = atomicAdd(&scnt, 1);
            if (pos < CCAP)
                scand[pos] = ((u64)sb[t] << 32) | (unsigned)(tid + t * T1);
        }
    }
    __syncthreads();

    // ---------------- phase 1b: warp-0 extract (proven) --------------------
    if (w == 0) {
        const int n = scnt;
        u64 fk[NSEL];
        u64 prev = 0;

        if (n <= CCAP) {
            u64 ck[CCAP / 32];
#pragma unroll
            for (int t = 0; t < CCAP / 32; ++t) {
                const int idx = lane + t * 32;
                ck[t] = (idx < n) ? scand[idx] : U64MAX;
            }
#pragma unroll 1
            for (int pass = 0; pass < NSEL; ++pass) {
                u64 lmin = U64MAX;
#pragma unroll
                for (int t = 0; t < CCAP / 32; ++t)
                    if (ck[t] > prev) lmin = u64min(lmin, ck[t]);
                u64 v = lmin;
#pragma unroll
                for (int off = 16; off > 0; off >>= 1) {
                    const u64 o = __shfl_xor_sync(0xffffffffu, v, off);
                    v = u64min(v, o);
                }
                fk[pass] = v;
                prev = v;
            }
        } else {
            // overflow fallback: deterministic full-row rescan (rare/never)
#pragma unroll 1
            for (int pass = 0; pass < NSEL; ++pass) {
                u64 lmin = U64MAX;
                for (int t = 0; t < NAG / 32; ++t) {
                    const int j = lane + t * 32;
                    const float2 v2 = *reinterpret_cast<const float2*>(row + (size_t)j * 4);
                    const float s = __fadd_rn(__fadd_rn(__fmul_rn(v2.x, v2.x), 1e-6f),
                                              __fadd_rn(__fmul_rn(v2.y, v2.y), 1e-6f));
                    const u64 k = ((u64)__float_as_uint(s) << 32) | (unsigned)j;
                    if (k > prev) lmin = u64min(lmin, k);
                }
                u64 v = lmin;
#pragma unroll
                for (int off = 16; off > 0; off >>= 1) {
                    const u64 o = __shfl_xor_sync(0xffffffffu, v, off);
                    v = u64min(v, o);
                }
                fk[pass] = v;
                prev = v;
            }
        }

        if (lane == 0) {
#pragma unroll
            for (int t = 0; t < NSEL; ++t) {
                const u64 k = fk[t];
                const float s  = __uint_as_float((unsigned)(k >> 32));
                const float dn = __fsqrt_rn(s);
                fk[t] = ((u64)__float_as_uint(dn) << 32) | (k & 0xFFFFFFFFULL);
            }
#pragma unroll
            for (int a = 1; a < NSEL; ++a) {
                const u64 key = fk[a];
                int b = a - 1;
#pragma unroll
                for (int q = 0; q < NSEL - 1; ++q) {
                    if (b >= 0 && fk[b] > key) { fk[b + 1] = fk[b]; b--; }
                }
                fk[b + 1] = key;
            }
#pragma unroll
            for (int t = 0; t < TOPK; ++t)
                sidx[t] = (int)(unsigned)(fk[t] & 0xFFFFFFFFULL);
        }
    }
    __syncthreads();

    // ---------------- phase 2a: features + mask/index outputs --------------
    if (tid < TOPK) {
        const int j = sidx[tid];
        const float4 v = *reinterpret_cast<const float4*>(
            x + ((size_t)i * NAG + (size_t)j) * 4);
        const float s2 = __fadd_rn(__fadd_rn(__fmul_rn(v.x, v.x), 1e-4f),
                                   __fadd_rn(__fmul_rn(v.y, v.y), 1e-4f));
        const float dn = __fsqrt_rn(s2);
        const float r  = rp[0];
        const float mk = (dn <= 1.0f) ? 1.0f : 0.0f;
        float* f = feats + tid * 8;
        f[0] = v.x; f[1] = v.y; f[2] = v.z; f[3] = v.w;
        f[4] = (i == j) ? 1.0f : 0.0f;
        f[5] = dn - r;
        masks[tid] = mk;
        const int item = i * TOPK + tid;
        out[NITEMS + item] = mk;
        out[2 * NITEMS + 2 * item + 0] = (float)i;
        out[2 * NITEMS + 2 * item + 1] = (float)j;
    }
    __syncthreads();

    // ---------------- phase 2b: layer1 (6 -> 64), H1s[o][it] ---------------
    {
        const int o  = tid & 63;
        const int g3 = (tid >> 6) * 3;       // item triple base (0,3,6,9)
        const float* wp = W1s + o * 6;
        const float w0 = wp[0], w1 = wp[1], w2 = wp[2];
        const float w3 = wp[3], w4v = wp[4], w5 = wp[5];
        const float bb = b1s[o];
#pragma unroll
        for (int e = 0; e < 3; ++e) {
            const int it = g3 + e;
            const float* f = feats + it * 8;
            float a = bb;
            a = fmaf(w0, f[0], a); a = fmaf(w1, f[1], a); a = fmaf(w2, f[2], a);
            a = fmaf(w3, f[3], a); a = fmaf(w4v, f[4], a); a = fmaf(w5, f[5], a);
            H1s[o * IST + it] = fmaxf(a, 0.0f);
        }
    }
    __syncthreads();

    // ------- phase 2c: layer2 GEMM (K=64), thread=(m, item-half) -----------
    {
        const int m  = tid & 127;
        const int ib = (tid >> 7) * 6;       // items ib..ib+5 (3 pairs)
        const float bv = b2[m];
        u64 a0 = pk2(bv, bv), a1 = a0, a2 = a0;

#pragma unroll 4
        for (int k = 0; k < 64; ++k) {
            const float wv = g_W2t[k * 128 + m];
            const u64 wd = pk2(wv, wv);
            const float* hrow = H1s + k * IST + ib;
            const u64 d0 = *reinterpret_cast<const u64*>(hrow);
            const u64 d1 = *reinterpret_cast<const u64*>(hrow + 2);
            const u64 d2 = *reinterpret_cast<const u64*>(hrow + 4);
            a0 = fma2(wd, d0, a0);
            a1 = fma2(wd, d1, a1);
            a2 = fma2(wd, d2, a2);
        }

        const float2 q0 = up2(a0);
        const float2 q1 = up2(a1);
        const float2 q2 = up2(a2);
        float* dst = H2s + m * IST + ib;
        dst[0] = fmaxf(q0.x, 0.f); dst[1] = fmaxf(q0.y, 0.f);
        dst[2] = fmaxf(q1.x, 0.f); dst[3] = fmaxf(q1.y, 0.f);
        dst[4] = fmaxf(q2.x, 0.f); dst[5] = fmaxf(q2.y, 0.f);
    }
    __syncthreads();

    // ------- phase 2d: layer3 (K=128 split in halves) + layer4 partials ----
    {
        const int o  = tid & 63;
        const int kh = (tid >> 6) & 1;       // k half
        const int pg = tid >> 7;             // pair group (items pg*6..pg*6+5)
        const int ib = pg * 6;
        const int k0 = kh * 64;
        u64 a0 = 0, a1 = 0, a2 = 0;          // bits(0,0) == packed +0.0f pair

#pragma unroll 4
        for (int kk = 0; kk < 64; ++kk) {
            const int k = k0 + kk;
            const float wv = g_W3t[k * 64 + o];
            const u64 wd = pk2(wv, wv);
            const float* hrow = H2s + k * IST + ib;
            const u64 d0 = *reinterpret_cast<const u64*>(hrow);
            const u64 d1 = *reinterpret_cast<const u64*>(hrow + 2);
            const u64 d2 = *reinterpret_cast<const u64*>(hrow + 4);
            a0 = fma2(wd, d0, a0);
            a1 = fma2(wd, d1, a1);
            a2 = fma2(wd, d2, a2);
        }

        if (kh) {                            // high half -> smem partials
            float* pp = part + (pg * 64 + o) * 6;
            const float2 q0 = up2(a0);
            const float2 q1 = up2(a1);
            const float2 q2 = up2(a2);
            pp[0] = q0.x; pp[1] = q0.y; pp[2] = q1.x;
            pp[3] = q1.y; pp[4] = q2.x; pp[5] = q2.y;
        }
        __syncthreads();

        if (!kh) {                           // low half combines + layer4
            const float* pp = part + (pg * 64 + o) * 6;
            const float bb = b3[o];
            const float wo = W4[o];
            const float2 q0 = up2(a0);
            const float2 q1 = up2(a1);
            const float2 q2 = up2(a2);
            float* rd = H1s + o * IST + ib;  // red aliases H1s (dead now)
            rd[0] = wo * fmaxf(q0.x + pp[0] + bb, 0.f);
            rd[1] = wo * fmaxf(q0.y + pp[1] + bb, 0.f);
            rd[2] = wo * fmaxf(q1.x + pp[2] + bb, 0.f);
            rd[3] = wo * fmaxf(q1.y + pp[3] + bb, 0.f);
            rd[4] = wo * fmaxf(q2.x + pp[4] + bb, 0.f);
            rd[5] = wo * fmaxf(q2.y + pp[5] + bb, 0.f);
        }
    }
    __syncthreads();

    // ---------------- phase 2e: final 64-way sum per item ------------------
    if (tid < TOPK) {
        float s = 0.f;
#pragma unroll
        for (int o = 0; o < 64; ++o) s += H1s[o * IST + tid];
        out[i * TOPK + tid] = (s + b4[0]) * masks[tid];
    }
}

extern "C" void kernel_launch(void* const* d_in, const int* in_sizes, int n_in,
                              void* d_out, int out_size) {
    const float* x  = (const float*)d_in[0];
    const float* r  = (const float*)d_in[1];
    const float* W1 = (const float*)d_in[2];
    const float* b1 = (const float*)d_in[3];
    const float* W2 = (const float*)d_in[4];
    const float* b2 = (const float*)d_in[5];
    const float* W3 = (const float*)d_in[6];
    const float* b3 = (const float*)d_in[7];
    const float* W4 = (const float*)d_in[8];
    const float* b4 = (const float*)d_in[9];
    float* out = (float*)d_out;

    transpose_kernel<<<32, T1>>>(W2, W3);
    fused_all_kernel<<<NAG, T1>>>(x, r, W1, b1, b2, b3, W4, b4, out);
}

// round 16
// speedup vs baseline: 1.3100x; 1.3100x over previous
#include <cuda_runtime.h>
#include <cstdint>

#define NAG   4096
#define TOPK  12
#define NSEL  13                 // extract 13, fix up ordering with real sqrt
#define NITEMS (NAG * TOPK)      // 49152
#define T1    256
#define EPT   16                 // elements per thread = 4096/256
#define CCAP  256                // per-row candidate capacity
#define ROWS  4                  // agent rows per block
#define NIT   48                 // items per block = ROWS*TOPK
#define ISTR  50                 // item stride (floats): even (u64 align), 2-way max
#define DSM_FLOATS ((64 + 128) * ISTR)
#define DSM_BYTES  (DSM_FLOATS * 4)      // 38,400 B (<48KB, no attribute needed)

#define U64MAX 0xFFFFFFFFFFFFFFFFULL
typedef unsigned long long u64;

__device__ float g_W2t[64 * 128];        // [k][m]
__device__ float g_W3t[128 * 64];        // [k][o]

static __device__ __forceinline__ u64 u64min(u64 a, u64 b) { return (b < a) ? b : a; }

// ---- packed f32x2 helpers (bitwise identical to two scalar fmaf's) --------
static __device__ __forceinline__ u64 pk2(float lo, float hi) {
    u64 r;
    asm("mov.b64 %0, {%1, %2};" : "=l"(r) : "f"(lo), "f"(hi));
    return r;
}
static __device__ __forceinline__ u64 fma2(u64 a, u64 b, u64 c) {
    u64 d;
    asm("fma.rn.f32x2 %0, %1, %2, %3;" : "=l"(d) : "l"(a), "l"(b), "l"(c));
    return d;
}
static __device__ __forceinline__ float2 up2(u64 v) {
    float2 f;
    asm("mov.b64 {%0, %1}, %2;" : "=f"(f.x), "=f"(f.y) : "l"(v));
    return f;
}

// ---------------------------------------------------------------------------
// Kernel T: transpose W2 -> g_W2t [k][m], W3 -> g_W3t [k][o].
// ---------------------------------------------------------------------------
__global__ void __launch_bounds__(T1) transpose_kernel(
    const float* __restrict__ W2, const float* __restrict__ W3)
{
    const int g = blockIdx.x * T1 + threadIdx.x;
    const int stride = gridDim.x * T1;
    for (int s = g; s < 128 * 64; s += stride) {
        const int m = s >> 6, k = s & 63;
        g_W2t[k * 128 + m] = W2[s];
    }
    for (int s = g; s < 64 * 128; s += stride) {
        const int o = s >> 7, m = s & 127;
        g_W3t[m * 64 + o] = W3[s];
    }
}

// ---------------------------------------------------------------------------
// Fused kernel: block = 4 agent rows.
//  Phase 1 (x4, proven): stream row, threshold filter (max of 16 half-warp
//    minima => >=16 candidates), per-row smem candidate buffer.
//  Phase 1b: warps 0..3 extract their row in PARALLEL (13 exact extract-min
//    passes + monotone-sqrt re-key fixup; overflow -> deterministic rescan).
//  Phase 2: 48-item MLP (round-12-style efficient tiles):
//    layer1 thread=(o, 12-item group); layer2 thread=4m x 6i (3 f32x2 pairs,
//    weights LDG.128 per 8 lanes); layer3 thread=2o x 6i K=128; fused layer4
//    partials -> 32-way sum.
//  Blocks de-phase so DRAM streaming overlaps other blocks' FFMA bursts.
// ---------------------------------------------------------------------------
__global__ void __launch_bounds__(T1) fused_all_kernel(
    const float* __restrict__ x,  const float* __restrict__ rp,
    const float* __restrict__ W1, const float* __restrict__ b1,
    const float* __restrict__ b2, const float* __restrict__ b3,
    const float* __restrict__ W4, const float* __restrict__ b4,
    float* __restrict__ out)
{
    extern __shared__ float dsm[];
    float* H1s = dsm;                    // [64][ISTR]
    float* H2s = dsm + 64 * ISTR;        // [128][ISTR]
    u64*   scand = reinterpret_cast<u64*>(H2s);   // [ROWS*CCAP], dead by stage B
    float* red = H1s;                    // layer4 partials alias H1s

    __shared__ float    feats[NIT * 8];
    __shared__ float    W1s[64 * 6];
    __shared__ float    b1s[64];
    __shared__ float    masks[NIT];
    __shared__ int      sidx[NIT];
    __shared__ unsigned tmin16[16];
    __shared__ unsigned sthresh;
    __shared__ int      scnt4[ROWS];

    const int tid  = threadIdx.x;
    const int w    = tid >> 5;
    const int lane = tid & 31;
    const int i4   = blockIdx.x * ROWS;

    for (int s = tid; s < 384; s += T1) W1s[s] = W1[s];
    if (tid < 64) b1s[tid] = b1[tid];
    if (tid < ROWS) scnt4[tid] = 0;

    // ---------------- phase 1: per-row streaming filter x4 -----------------
#pragma unroll 1
    for (int r = 0; r < ROWS; ++r) {
        const float* row = x + (size_t)(i4 + r) * (NAG * 4);
        unsigned sb[EPT];
#pragma unroll
        for (int t = 0; t < EPT; ++t) {
            const int j = tid + t * T1;
            const float2 v = __ldcs(reinterpret_cast<const float2*>(row + (size_t)j * 4));
            const float s = __fadd_rn(__fadd_rn(__fmul_rn(v.x, v.x), 1e-6f),
                                      __fadd_rn(__fmul_rn(v.y, v.y), 1e-6f));
            sb[t] = __float_as_uint(s);
        }

        unsigned mymin = sb[0];
#pragma unroll
        for (int t = 1; t < EPT; ++t) mymin = (sb[t] < mymin) ? sb[t] : mymin;

        unsigned h = mymin;
#pragma unroll
        for (int off = 1; off <= 8; off <<= 1) {
            const unsigned o = __shfl_xor_sync(0xffffffffu, h, off);
            h = (o < h) ? o : h;
        }
        if ((lane & 15) == 0) tmin16[w * 2 + (lane >> 4)] = h;
        __syncthreads();

        if (w == 0 && lane < 16) {
            const unsigned mx = __reduce_max_sync(0xFFFFu, tmin16[lane]);
            if (lane == 0) sthresh = mx;
        }
        __syncthreads();

        const unsigned thr = sthresh;
        u64* cand = scand + r * CCAP;
#pragma unroll
        for (int t = 0; t < EPT; ++t) {
            if (sb[t] <= thr) {
                const int pos = atomicAdd(&scnt4[r], 1);
                if (pos < CCAP)
                    cand[pos] = ((u64)sb[t] << 32) | (unsigned)(tid + t * T1);
            }
        }
    }
    __syncthreads();

    // ---------------- phase 1b: warps 0..3 extract their row ---------------
    if (w < ROWS) {
        const int n = scnt4[w];
        const u64* cand = scand + w * CCAP;
        u64 fk[NSEL];
        u64 prev = 0;

        if (n <= CCAP) {
            u64 ck[CCAP / 32];
#pragma unroll
            for (int t = 0; t < CCAP / 32; ++t) {
                const int idx = lane + t * 32;
                ck[t] = (idx < n) ? cand[idx] : U64MAX;
            }
#pragma unroll 1
            for (int pass = 0; pass < NSEL; ++pass) {
                u64 lmin = U64MAX;
#pragma unroll
                for (int t = 0; t < CCAP / 32; ++t)
                    if (ck[t] > prev) lmin = u64min(lmin, ck[t]);
                u64 v = lmin;
#pragma unroll
                for (int off = 16; off > 0; off >>= 1) {
                    const u64 o = __shfl_xor_sync(0xffffffffu, v, off);
                    v = u64min(v, o);
                }
                fk[pass] = v;
                prev = v;
            }
        } else {
            // overflow fallback: deterministic full-row rescan (rare/never)
            const float* row = x + (size_t)(i4 + w) * (NAG * 4);
#pragma unroll 1
            for (int pass = 0; pass < NSEL; ++pass) {
                u64 lmin = U64MAX;
                for (int t = 0; t < NAG / 32; ++t) {
                    const int j = lane + t * 32;
                    const float2 v2 = *reinterpret_cast<const float2*>(row + (size_t)j * 4);
                    const float s = __fadd_rn(__fadd_rn(__fmul_rn(v2.x, v2.x), 1e-6f),
                                              __fadd_rn(__fmul_rn(v2.y, v2.y), 1e-6f));
                    const u64 k = ((u64)__float_as_uint(s) << 32) | (unsigned)j;
                    if (k > prev) lmin = u64min(lmin, k);
                }
                u64 v = lmin;
#pragma unroll
                for (int off = 16; off > 0; off >>= 1) {
                    const u64 o = __shfl_xor_sync(0xffffffffu, v, off);
                    v = u64min(v, o);
                }
                fk[pass] = v;
                prev = v;
            }
        }

        if (lane == 0) {
#pragma unroll
            for (int t = 0; t < NSEL; ++t) {
                const u64 k = fk[t];
                const float s  = __uint_as_float((unsigned)(k >> 32));
                const float dn = __fsqrt_rn(s);
                fk[t] = ((u64)__float_as_uint(dn) << 32) | (k & 0xFFFFFFFFULL);
            }
#pragma unroll
            for (int a = 1; a < NSEL; ++a) {
                const u64 key = fk[a];
                int b = a - 1;
#pragma unroll
                for (int q = 0; q < NSEL - 1; ++q) {
                    if (b >= 0 && fk[b] > key) { fk[b + 1] = fk[b]; b--; }
                }
                fk[b + 1] = key;
            }
#pragma unroll
            for (int t = 0; t < TOPK; ++t)
                sidx[w * TOPK + t] = (int)(unsigned)(fk[t] & 0xFFFFFFFFULL);
        }
    }
    __syncthreads();

    // ---------------- phase 2a: features + mask/index outputs --------------
    if (tid < NIT) {
        const int i = i4 + tid / TOPK;
        const int j = sidx[tid];
        const float4 v = *reinterpret_cast<const float4*>(
            x + ((size_t)i * NAG + (size_t)j) * 4);
        const float s2 = __fadd_rn(__fadd_rn(__fmul_rn(v.x, v.x), 1e-4f),
                                   __fadd_rn(__fmul_rn(v.y, v.y), 1e-4f));
        const float dn = __fsqrt_rn(s2);
        const float r  = rp[0];
        const float mk = (dn <= 1.0f) ? 1.0f : 0.0f;
        float* f = feats + tid * 8;
        f[0] = v.x; f[1] = v.y; f[2] = v.z; f[3] = v.w;
        f[4] = (i == j) ? 1.0f : 0.0f;
        f[5] = dn - r;
        masks[tid] = mk;
        const int item = i4 * TOPK + tid;
        out[NITEMS + item] = mk;
        out[2 * NITEMS + 2 * item + 0] = (float)i;
        out[2 * NITEMS + 2 * item + 1] = (float)j;
    }
    __syncthreads();

    // ---------------- phase 2b: layer1 (6 -> 64) -> H1s[o][it] -------------
    {
        const int o  = tid & 63;
        const int g  = tid >> 6;             // 4 groups x 12 items
        const float* wp = W1s + o * 6;
        const float w0 = wp[0], w1 = wp[1], w2 = wp[2];
        const float w3 = wp[3], w4v = wp[4], w5 = wp[5];
        const float bb = b1s[o];
#pragma unroll
        for (int e = 0; e < 12; ++e) {
            const int it = g * 12 + e;
            const float* f = feats + it * 8;
            float a = bb;
            a = fmaf(w0, f[0], a); a = fmaf(w1, f[1], a); a = fmaf(w2, f[2], a);
            a = fmaf(w3, f[3], a); a = fmaf(w4v, f[4], a); a = fmaf(w5, f[5], a);
            H1s[o * ISTR + it] = fmaxf(a, 0.0f);
        }
    }
    __syncthreads();

    // ------- phase 2c: layer2 GEMM (K=64), thread = 4m x 6i, f32x2 ---------
    {
        const int m0 = (tid >> 3) * 4;       // 0..124
        const int i0 = (tid & 7) * 6;        // 0..42 (3 pairs)

        u64 acc[4][3];
#pragma unroll
        for (int mm = 0; mm < 4; ++mm) {
            const float b = b2[m0 + mm];
            const u64 pb = pk2(b, b);
            acc[mm][0] = pb; acc[mm][1] = pb; acc[mm][2] = pb;
        }

#pragma unroll 4
        for (int k = 0; k < 64; ++k) {
            const float4 a = *reinterpret_cast<const float4*>(g_W2t + k * 128 + m0);
            const float* hrow = H1s + k * ISTR + i0;
            const u64 d0 = *reinterpret_cast<const u64*>(hrow);
            const u64 d1 = *reinterpret_cast<const u64*>(hrow + 2);
            const u64 d2 = *reinterpret_cast<const u64*>(hrow + 4);
            const u64 ax = pk2(a.x, a.x);
            const u64 ay = pk2(a.y, a.y);
            const u64 az = pk2(a.z, a.z);
            const u64 aw = pk2(a.w, a.w);
            acc[0][0] = fma2(ax, d0, acc[0][0]); acc[0][1] = fma2(ax, d1, acc[0][1]);
            acc[0][2] = fma2(ax, d2, acc[0][2]);
            acc[1][0] = fma2(ay, d0, acc[1][0]); acc[1][1] = fma2(ay, d1, acc[1][1]);
            acc[1][2] = fma2(ay, d2, acc[1][2]);
            acc[2][0] = fma2(az, d0, acc[2][0]); acc[2][1] = fma2(az, d1, acc[2][1]);
            acc[2][2] = fma2(az, d2, acc[2][2]);
            acc[3][0] = fma2(aw, d0, acc[3][0]); acc[3][1] = fma2(aw, d1, acc[3][1]);
            acc[3][2] = fma2(aw, d2, acc[3][2]);
        }
        __syncthreads();                     // scand (aliasing H2s) fully dead

#pragma unroll
        for (int mm = 0; mm < 4; ++mm) {
            float* dst = H2s + (m0 + mm) * ISTR + i0;
            const float2 p0 = up2(acc[mm][0]);
            const float2 p1 = up2(acc[mm][1]);
            const float2 p2 = up2(acc[mm][2]);
            float2 s0, s1, s2;
            s0.x = fmaxf(p0.x, 0.f); s0.y = fmaxf(p0.y, 0.f);
            s1.x = fmaxf(p1.x, 0.f); s1.y = fmaxf(p1.y, 0.f);
            s2.x = fmaxf(p2.x, 0.f); s2.y = fmaxf(p2.y, 0.f);
            *reinterpret_cast<float2*>(dst)     = s0;
            *reinterpret_cast<float2*>(dst + 2) = s1;
            *reinterpret_cast<float2*>(dst + 4) = s2;
        }
    }
    __syncthreads();

    // ------- phase 2d: layer3 GEMM (K=128), thread = 2o x 6i + layer4 ------
    {
        const int o0 = (tid >> 3) * 2;       // 0..62
        const int c  = (tid & 7) * 6;        // 0..42

        u64 acc[2][3];
#pragma unroll
        for (int oo = 0; oo < 2; ++oo) {
            const float b = b3[o0 + oo];
            const u64 pb = pk2(b, b);
            acc[oo][0] = pb; acc[oo][1] = pb; acc[oo][2] = pb;
        }

#pragma unroll 4
        for (int k = 0; k < 128; ++k) {
            const float2 a = *reinterpret_cast<const float2*>(g_W3t + k * 64 + o0);
            const float* hrow = H2s + k * ISTR + c;
            const u64 d0 = *reinterpret_cast<const u64*>(hrow);
            const u64 d1 = *reinterpret_cast<const u64*>(hrow + 2);
            const u64 d2 = *reinterpret_cast<const u64*>(hrow + 4);
            const u64 ax = pk2(a.x, a.x);
            const u64 ay = pk2(a.y, a.y);
            acc[0][0] = fma2(ax, d0, acc[0][0]); acc[0][1] = fma2(ax, d1, acc[0][1]);
            acc[0][2] = fma2(ax, d2, acc[0][2]);
            acc[1][0] = fma2(ay, d0, acc[1][0]); acc[1][1] = fma2(ay, d1, acc[1][1]);
            acc[1][2] = fma2(ay, d2, acc[1][2]);
        }

        // relu + layer4 partials over this thread's 2 o's
        const float2 w4 = *reinterpret_cast<const float2*>(W4 + o0);
        const int og = tid >> 3;             // 0..31
        float p[6];
#pragma unroll
        for (int pr = 0; pr < 3; ++pr) {
            const float2 v0 = up2(acc[0][pr]);
            const float2 v1 = up2(acc[1][pr]);
            float a0 = __fmul_rn(w4.x, fmaxf(v0.x, 0.f));
            a0 = fmaf(w4.y, fmaxf(v1.x, 0.f), a0);
            float a1 = __fmul_rn(w4.x, fmaxf(v0.y, 0.f));
            a1 = fmaf(w4.y, fmaxf(v1.y, 0.f), a1);
            p[2 * pr]     = a0;
            p[2 * pr + 1] = a1;
        }
        __syncthreads();                     // H1s reads (stage B) long done
        float* rd = red + og * ISTR + c;
        rd[0] = p[0]; rd[1] = p[1]; rd[2] = p[2];
        rd[3] = p[3]; rd[4] = p[4]; rd[5] = p[5];
    }
    __syncthreads();

    // ---------------- phase 2e: final 32-way sum per item ------------------
    if (tid < NIT) {
        float s = 0.f;
#pragma unroll
        for (int og = 0; og < 32; ++og) s += red[og * ISTR + tid];
        out[i4 * TOPK + tid] = (s + b4[0]) * masks[tid];
    }
}

extern "C" void kernel_launch(void* const* d_in, const int* in_sizes, int n_in,
                              void* d_out, int out_size) {
    const float* x  = (const float*)d_in[0];
    const float* r  = (const float*)d_in[1];
    const float* W1 = (const float*)d_in[2];
    const float* b1 = (const float*)d_in[3];
    const float* W2 = (const float*)d_in[4];
    const float* b2 = (const float*)d_in[5];
    const float* W3 = (const float*)d_in[6];
    const float* b3 = (const float*)d_in[7];
    const float* W4 = (const float*)d_in[8];
    const float* b4 = (const float*)d_in[9];
    float* out = (float*)d_out;

    transpose_kernel<<<32, T1>>>(W2, W3);
    fused_all_kernel<<<NAG / ROWS, T1, DSM_BYTES>>>(
        x, r, W1, b1, b2, b3, W4, b4, out);
}